// round 6
// baseline (speedup 1.0000x reference)
#include <cuda_runtime.h>
#include <cuda_fp16.h>

// DAGNN: CSR build, then ONE persistent cooperative kernel doing
// prep + 10x SpMM hops (fp16 ping-pong, L2-hot) + fused sigmoid pooling
// (accumulators in SMEM), with software grid barriers between hops.
// N=100000, D=64, E=1600000, K=10.

#define MAX_N 100000
#define MAX_E 1600000
#define D 64
#define KHOPS 10
#define FULLMASK 0xffffffffu

#define NSM 148
#define BPSM 4
#define NBLOCKS (NSM * BPSM)          // 592, co-resident by __launch_bounds__(256,4)
#define TPB 256
#define WPB (TPB / 32)                // 8 warps/block
#define TOTAL_WARPS (NBLOCKS * WPB)   // 4736
#define NPW 22                        // ceil(100000/4736) -> 22 nodes per warp

// ---------------- device scratch (static: allocation-free rule) ----------------
__device__ __align__(256) __half g_bufA[(size_t)MAX_N * D];  // ping
__device__ __align__(256) __half g_bufB[(size_t)MAX_N * D];  // pong
__device__ float g_norm[MAX_N];      // rsqrt(max(deg,1))
__device__ float g_norm2[MAX_N];     // 1/max(deg,1)
__device__ int   g_deg[MAX_N];
__device__ int   g_cursor[MAX_N];
__device__ int   g_rowptr[MAX_N + 1];
__device__ int   g_csr_src[MAX_E];
__device__ int   g_idx64;            // 1 if src/dst are int64, 0 if int32
__device__ int   g_bar[16];          // grid-barrier counters (zeroed every launch)

// ---------------- k1: init scratch + barrier counters + dtype probe ------------
__global__ void init_kernel(const void* __restrict__ dst, int n) {
    if (blockIdx.x == 0) {
        // int64 values < 2^31 have zero odd 32-bit words; int32 ids are random.
        const unsigned* w = (const unsigned*)dst;
        int ok = (w[2 * threadIdx.x + 1] == 0u) ? 1 : 0;
        int all = __syncthreads_and(ok);
        if (threadIdx.x == 0) g_idx64 = all;
        if (threadIdx.x < 16) g_bar[threadIdx.x] = 0;
    }
    for (int i = blockIdx.x * blockDim.x + threadIdx.x; i < n;
         i += gridDim.x * blockDim.x) {
        g_deg[i] = 0;
        g_cursor[i] = 0;
    }
}

__device__ __forceinline__ int read_idx(const void* p, int i, int is64) {
    if (is64) return (int)((const long long*)p)[i];
    return ((const int*)p)[i];
}

// ---------------- k2: degree count ----------------
__global__ void deg_kernel(const void* __restrict__ dst, int e) {
    int is64 = g_idx64;
    for (int i = blockIdx.x * blockDim.x + threadIdx.x; i < e;
         i += gridDim.x * blockDim.x) {
        atomicAdd(&g_deg[read_idx(dst, i, is64)], 1);
    }
}

// ---------------- k3: norm terms + exclusive scan (one block) ----------------
__global__ void normscan_kernel(int n) {
    __shared__ int part[1024];
    int t = threadIdx.x;
    int chunk = (n + 1023) / 1024;
    int beg = t * chunk;
    int end = beg + chunk;
    if (beg > n) beg = n;
    if (end > n) end = n;
    int s = 0;
    for (int i = beg; i < end; ++i) {
        int d = g_deg[i];
        float df = fmaxf((float)d, 1.0f);
        g_norm2[i] = 1.0f / df;
        g_norm[i] = rsqrtf(df);
        s += d;
    }
    part[t] = s;
    __syncthreads();
    if (t == 0) {
        int acc = 0;
        for (int i = 0; i < 1024; ++i) { int v = part[i]; part[i] = acc; acc += v; }
    }
    __syncthreads();
    int acc = part[t];
    for (int i = beg; i < end; ++i) { g_rowptr[i] = acc; acc += g_deg[i]; }
    if (t == 1023) g_rowptr[n] = acc;
}

// ---------------- k4: CSR fill ----------------
__global__ void fill_kernel(const void* __restrict__ src,
                            const void* __restrict__ dst, int e) {
    int is64 = g_idx64;
    for (int i = blockIdx.x * blockDim.x + threadIdx.x; i < e;
         i += gridDim.x * blockDim.x) {
        int d = read_idx(dst, i, is64);
        int p = atomicAdd(&g_cursor[d], 1);
        g_csr_src[g_rowptr[d] + p] = read_idx(src, i, is64);
    }
}

// ---------------- grid barrier (all NBLOCKS co-resident) ----------------
__device__ __forceinline__ int ld_acq(int* p) {
    int v;
    asm volatile("ld.acquire.gpu.s32 %0, [%1];" : "=r"(v) : "l"(p));
    return v;
}

__device__ __forceinline__ void grid_barrier(int phase) {
    __syncthreads();
    if (threadIdx.x == 0) {
        __threadfence();
        atomicAdd(&g_bar[phase], 1);
        while (ld_acq(&g_bar[phase]) < NBLOCKS) { }
    }
    __syncthreads();
}

// ---------------- k5: persistent prep + hops + pooling ----------------
__global__ void __launch_bounds__(TPB, BPSM)
dagnn_kernel(const float* __restrict__ feat,
             const float* __restrict__ s,
             float* __restrict__ out, int n) {
    // SMEM pooling accumulators: [warp][node][lane] as float2 -> 45056 B
    __shared__ float2 acc[WPB * NPW * 32];

    int wlocal = threadIdx.x >> 5;
    int lane = threadIdx.x & 31;
    int w = blockIdx.x * WPB + wlocal;     // global warp id
    int node0 = w * NPW;

    float2 sv = ((const float2*)s)[lane];
    const __half2* qA = (const __half2*)g_bufA;
    __half2* qB = (__half2*)g_bufB;

    // ---- prep: acc = sig(f.s)*f ; q0 = norm*f ----
    #pragma unroll 2
    for (int nl = 0; nl < NPW; ++nl) {
        int node = node0 + nl;
        if (node >= n) break;
        int base = node * 32 + lane;
        float2 f = ((const float2*)feat)[base];
        float dot = f.x * sv.x + f.y * sv.y;
        #pragma unroll
        for (int off = 16; off; off >>= 1) dot += __shfl_xor_sync(FULLMASK, dot, off);
        float sig = 1.0f / (1.0f + __expf(-dot));
        float2 a; a.x = sig * f.x; a.y = sig * f.y;
        acc[(wlocal * NPW + nl) * 32 + lane] = a;
        float nm = g_norm[node];
        float2 g; g.x = nm * f.x; g.y = nm * f.y;
        ((__half2*)g_bufA)[base] = __float22half2_rn(g);
    }

    grid_barrier(0);

    // ---- hops ----
    const __half2* qin = qA;
    __half2* qout = qB;
    #pragma unroll 1
    for (int t = 1; t <= KHOPS; ++t) {
        for (int nl = 0; nl < NPW; ++nl) {
            int node = node0 + nl;
            if (node >= n) break;
            int beg = g_rowptr[node];
            int end = g_rowptr[node + 1];
            float a0 = 0.0f, a1 = 0.0f;
            #pragma unroll 4
            for (int j = beg; j < end; ++j) {
                int sn = g_csr_src[j];                           // uniform, L1-hot
                float2 v = __half22float2(qin[sn * 32 + lane]);  // 128B coalesced
                a0 += v.x; a1 += v.y;
            }
            float nm = g_norm[node];
            float h0 = nm * a0, h1 = nm * a1;                    // h_t
            float dot = h0 * sv.x + h1 * sv.y;
            #pragma unroll
            for (int off = 16; off; off >>= 1) dot += __shfl_xor_sync(FULLMASK, dot, off);
            float sig = 1.0f / (1.0f + __expf(-dot));
            float2* ap = &acc[(wlocal * NPW + nl) * 32 + lane];
            float2 a = *ap;
            a.x += sig * h0; a.y += sig * h1;
            *ap = a;
            float n2 = g_norm2[node];
            float2 g; g.x = n2 * a0; g.y = n2 * a1;              // q_t = norm*h_t
            qout[node * 32 + lane] = __float22half2_rn(g);
        }
        if (t < KHOPS) grid_barrier(t);
        const __half2* tmp = qin; qin = qout; qout = (__half2*)tmp;
    }

    // ---- write pooled output ----
    for (int nl = 0; nl < NPW; ++nl) {
        int node = node0 + nl;
        if (node >= n) break;
        ((float2*)out)[node * 32 + lane] = acc[(wlocal * NPW + nl) * 32 + lane];
    }
}

// ---------------- launch ----------------
extern "C" void kernel_launch(void* const* d_in, const int* in_sizes, int n_in,
                              void* d_out, int out_size) {
    const float* feat = (const float*)d_in[0];
    const float* s    = (const float*)d_in[1];
    const void*  src  = d_in[2];
    const void*  dst  = d_in[3];
    float* out = (float*)d_out;

    int n = in_sizes[0] / D;
    int e = in_sizes[2];

    const int T = 256;
    int blkN = (n + T - 1) / T;
    int blkE = (e + T - 1) / T; if (blkE > 2048) blkE = 2048;

    init_kernel<<<blkN, T>>>(dst, n);          // zeroes deg/cursor/barriers, probe
    deg_kernel<<<blkE, T>>>(dst, e);
    normscan_kernel<<<1, 1024>>>(n);
    fill_kernel<<<blkE, T>>>(src, dst, e);
    dagnn_kernel<<<NBLOCKS, TPB>>>(feat, s, out, n);
    (void)n_in; (void)out_size;
}

// round 8
// speedup vs baseline: 1.8825x; 1.8825x over previous
#include <cuda_runtime.h>
#include <cuda_fp16.h>

// DAGNN: CSR build + 10x SpMM hops (fp16 q-buffers, 5-slot rotation),
// pooling grouped every 5 hops (own-row re-reads, one out RMW per group).
// N=100000, D=64, E=1600000, K=10.

#define MAX_N 100000
#define MAX_E 1600000
#define D 64
#define FULLMASK 0xffffffffu
#define NBUF 5
#define ROWB 128                      // bytes per node row (64 * fp16)

// ---------------- device scratch (static: allocation-free rule) ----------------
__device__ __align__(256) __half g_q[NBUF * (size_t)MAX_N * D];  // 64 MB
__device__ float g_norm[MAX_N];      // rsqrt(max(deg,1))
__device__ float g_norm2[MAX_N];     // 1/max(deg,1)
__device__ float g_invn[MAX_N];      // sqrt(max(deg,1)) = 1/norm
__device__ int   g_deg[MAX_N];
__device__ int   g_cursor[MAX_N];
__device__ int   g_rowptr[MAX_N + 1];
__device__ int   g_csr_src[MAX_E];
__device__ int   g_idx64;            // 1 if src/dst are int64, 0 if int32

// ---------------- k1: init + dtype probe ----------------
__global__ void init_kernel(const void* __restrict__ dst, int n) {
    if (blockIdx.x == 0) {
        // int64 values < 2^31 have zero odd 32-bit words; int32 ids are random.
        const unsigned* w = (const unsigned*)dst;
        int ok = (w[2 * threadIdx.x + 1] == 0u) ? 1 : 0;
        int all = __syncthreads_and(ok);
        if (threadIdx.x == 0) g_idx64 = all;
    }
    for (int i = blockIdx.x * blockDim.x + threadIdx.x; i < n;
         i += gridDim.x * blockDim.x) {
        g_deg[i] = 0;
        g_cursor[i] = 0;
    }
}

__device__ __forceinline__ int read_idx(const void* p, int i, int is64) {
    if (is64) return (int)((const long long*)p)[i];
    return ((const int*)p)[i];
}

// ---------------- k2: degree count ----------------
__global__ void deg_kernel(const void* __restrict__ dst, int e) {
    int is64 = g_idx64;
    for (int i = blockIdx.x * blockDim.x + threadIdx.x; i < e;
         i += gridDim.x * blockDim.x) {
        atomicAdd(&g_deg[read_idx(dst, i, is64)], 1);
    }
}

// ---------------- k3: norm terms + exclusive scan (one block) ----------------
__global__ void normscan_kernel(int n) {
    __shared__ int part[1024];
    int t = threadIdx.x;
    int chunk = (n + 1023) / 1024;
    int beg = t * chunk;
    int end = beg + chunk;
    if (beg > n) beg = n;
    if (end > n) end = n;
    int s = 0;
    for (int i = beg; i < end; ++i) {
        int d = g_deg[i];
        float df = fmaxf((float)d, 1.0f);
        g_norm2[i] = 1.0f / df;
        g_norm[i] = rsqrtf(df);
        g_invn[i] = sqrtf(df);
        s += d;
    }
    part[t] = s;
    __syncthreads();
    if (t == 0) {
        int acc = 0;
        for (int i = 0; i < 1024; ++i) { int v = part[i]; part[i] = acc; acc += v; }
    }
    __syncthreads();
    int acc = part[t];
    for (int i = beg; i < end; ++i) { g_rowptr[i] = acc; acc += g_deg[i]; }
    if (t == 1023) g_rowptr[n] = acc;
}

// ---------------- k4: CSR fill ----------------
__global__ void fill_kernel(const void* __restrict__ src,
                            const void* __restrict__ dst, int e) {
    int is64 = g_idx64;
    for (int i = blockIdx.x * blockDim.x + threadIdx.x; i < e;
         i += gridDim.x * blockDim.x) {
        int d = read_idx(dst, i, is64);
        int p = atomicAdd(&g_cursor[d], 1);
        g_csr_src[g_rowptr[d] + p] = read_idx(src, i, is64);
    }
}

// ---------------- k5: prep: out = sig(f.s)*f (write-only), q0 = norm*f --------
__global__ void prep_kernel(const float* __restrict__ feat,
                            const float* __restrict__ s,
                            float* __restrict__ out,
                            __half2* __restrict__ q0, int n) {
    int warp = (blockIdx.x * blockDim.x + threadIdx.x) >> 5;
    int lane = threadIdx.x & 31;
    if (warp >= n) return;
    int base = warp * 32 + lane;
    float2 f = ((const float2*)feat)[base];
    float2 sv = ((const float2*)s)[lane];
    float dot = f.x * sv.x + f.y * sv.y;
    #pragma unroll
    for (int off = 16; off; off >>= 1) dot += __shfl_xor_sync(FULLMASK, dot, off);
    float sig = 1.0f / (1.0f + __expf(-dot));
    float2 o; o.x = sig * f.x; o.y = sig * f.y;
    ((float2*)out)[base] = o;
    float nm = g_norm[warp];
    float2 g; g.x = nm * f.x; g.y = nm * f.y;
    q0[base] = __float22half2_rn(g);
}

// ---------------- gather helpers (paired-edge 64-bit loads) ----------------
// Lane p=lane&15 owns channels 4p..4p+3. Half-warp 0 loads edge j, half-warp 1
// loads edge j+1; after shfl_xor(16) combine, all lanes hold the full sums.
struct Acc4 { float a0, a1, a2, a3; };

__device__ __forceinline__ void gather_row(const char* __restrict__ qin,
                                           int beg, int end, int lane, int p,
                                           Acc4& A) {
    float a0 = 0.f, a1 = 0.f, a2 = 0.f, a3 = 0.f;
    int j = beg;
    #pragma unroll 4
    for (; j + 2 <= end; j += 2) {
        int sn0 = g_csr_src[j];
        int sn1 = g_csr_src[j + 1];
        int sn = (lane < 16) ? sn0 : sn1;
        uint2 v = *(const uint2*)(qin + (size_t)sn * ROWB + p * 8);
        float2 f0 = __half22float2(*(__half2*)&v.x);
        float2 f1 = __half22float2(*(__half2*)&v.y);
        a0 += f0.x; a1 += f0.y; a2 += f1.x; a3 += f1.y;
    }
    if (j < end && lane < 16) {
        int sn = g_csr_src[j];
        uint2 v = *(const uint2*)(qin + (size_t)sn * ROWB + p * 8);
        float2 f0 = __half22float2(*(__half2*)&v.x);
        float2 f1 = __half22float2(*(__half2*)&v.y);
        a0 += f0.x; a1 += f0.y; a2 += f1.x; a3 += f1.y;
    }
    a0 += __shfl_xor_sync(FULLMASK, a0, 16);
    a1 += __shfl_xor_sync(FULLMASK, a1, 16);
    a2 += __shfl_xor_sync(FULLMASK, a2, 16);
    a3 += __shfl_xor_sync(FULLMASK, a3, 16);
    A.a0 = a0; A.a1 = a1; A.a2 = a2; A.a3 = a3;
}

// dot of 4-channel-per-lane vector with s (channels duplicated across halves)
__device__ __forceinline__ float dot_s(float h0, float h1, float h2, float h3,
                                       float4 sv) {
    float d = h0 * sv.x + h1 * sv.y + h2 * sv.z + h3 * sv.w;
    #pragma unroll
    for (int off = 16; off; off >>= 1) d += __shfl_xor_sync(FULLMASK, d, off);
    return d * 0.5f;                  // each channel counted twice
}

// ---------------- hop (plain): q_t = norm2 * gather(q_{t-1}) ----------------
__global__ void hop_kernel(const char* __restrict__ qin,
                           char* __restrict__ qout, int n) {
    int warp = (blockIdx.x * blockDim.x + threadIdx.x) >> 5;
    int lane = threadIdx.x & 31;
    if (warp >= n) return;
    int p = lane & 15;
    Acc4 A;
    gather_row(qin, g_rowptr[warp], g_rowptr[warp + 1], lane, p, A);
    float n2 = g_norm2[warp];
    if (lane < 16) {
        __half2 h0 = __float22half2_rn(make_float2(n2 * A.a0, n2 * A.a1));
        __half2 h1 = __float22half2_rn(make_float2(n2 * A.a2, n2 * A.a3));
        uint2 w; w.x = *(unsigned*)&h0; w.y = *(unsigned*)&h1;
        *(uint2*)(qout + (size_t)warp * ROWB + p * 8) = w;
    }
}

// ---------------- hop + pool: also accumulate 5 hops' sig-weighted h ----------
__global__ void hop_pool_kernel(const char* __restrict__ qin,
                                char* __restrict__ qout,
                                const char* __restrict__ b1,
                                const char* __restrict__ b2,
                                const char* __restrict__ b3,
                                const char* __restrict__ b4,
                                const float* __restrict__ s,
                                float* __restrict__ out, int n) {
    int warp = (blockIdx.x * blockDim.x + threadIdx.x) >> 5;
    int lane = threadIdx.x & 31;
    if (warp >= n) return;
    int p = lane & 15;
    Acc4 A;
    gather_row(qin, g_rowptr[warp], g_rowptr[warp + 1], lane, p, A);

    float4 sv = ((const float4*)s)[p];
    float nm = g_norm[warp];
    float n2 = g_norm2[warp];
    float inv = g_invn[warp];

    // current hop contribution (h_t in registers)
    float h0 = nm * A.a0, h1 = nm * A.a1, h2 = nm * A.a2, h3 = nm * A.a3;
    float sig = 1.0f / (1.0f + __expf(-dot_s(h0, h1, h2, h3, sv)));
    float c0 = sig * h0, c1 = sig * h1, c2 = sig * h2, c3 = sig * h3;

    // 4 older hops from rotation buffers (own-row reads, L2-hot)
    const char* bufs[4] = { b1, b2, b3, b4 };
    #pragma unroll
    for (int b = 0; b < 4; ++b) {
        uint2 v = *(const uint2*)(bufs[b] + (size_t)warp * ROWB + p * 8);
        float2 f0 = __half22float2(*(__half2*)&v.x);
        float2 f1 = __half22float2(*(__half2*)&v.y);
        float e0 = inv * f0.x, e1 = inv * f0.y, e2 = inv * f1.x, e3 = inv * f1.y;
        float sg = 1.0f / (1.0f + __expf(-dot_s(e0, e1, e2, e3, sv)));
        c0 += sg * e0; c1 += sg * e1; c2 += sg * e2; c3 += sg * e3;
    }

    if (lane < 16) {
        __half2 w0 = __float22half2_rn(make_float2(n2 * A.a0, n2 * A.a1));
        __half2 w1 = __float22half2_rn(make_float2(n2 * A.a2, n2 * A.a3));
        uint2 w; w.x = *(unsigned*)&w0; w.y = *(unsigned*)&w1;
        *(uint2*)(qout + (size_t)warp * ROWB + p * 8) = w;

        float4* op = (float4*)out + warp * 16 + p;
        float4 o = *op;
        o.x += c0; o.y += c1; o.z += c2; o.w += c3;
        *op = o;
    }
}

// ---------------- launch ----------------
extern "C" void kernel_launch(void* const* d_in, const int* in_sizes, int n_in,
                              void* d_out, int out_size) {
    const float* feat = (const float*)d_in[0];
    const float* s    = (const float*)d_in[1];
    const void*  src  = d_in[2];
    const void*  dst  = d_in[3];
    float* out = (float*)d_out;

    int n = in_sizes[0] / D;
    int e = in_sizes[2];

    char* qbase;
    cudaGetSymbolAddress((void**)&qbase, g_q);
    const size_t BUF = (size_t)MAX_N * ROWB;
    char* B[NBUF];
    for (int i = 0; i < NBUF; ++i) B[i] = qbase + i * BUF;

    const int T = 256;
    int blkN = (n + T - 1) / T;
    int blkE = (e + T - 1) / T; if (blkE > 2048) blkE = 2048;
    int blkW = (int)(((size_t)n * 32 + T - 1) / T);   // one warp per node

    init_kernel<<<blkN, T>>>(dst, n);
    deg_kernel<<<blkE, T>>>(dst, e);
    normscan_kernel<<<1, 1024>>>(n);
    fill_kernel<<<blkE, T>>>(src, dst, e);
    prep_kernel<<<blkW, T>>>(feat, s, out, (__half2*)B[0], n);

    // hops: q_t lives in B[t % 5]; pool at t=5 (h1..h5) and t=10 (h6..h10)
    for (int t = 1; t <= 10; ++t) {
        const char* qin = B[(t - 1) % NBUF];
        char* qout = B[t % NBUF];
        if (t == 5 || t == 10) {
            hop_pool_kernel<<<blkW, T>>>(qin, qout, B[1], B[2], B[3], B[4],
                                         s, out, n);
        } else {
            hop_kernel<<<blkW, T>>>(qin, qout, n);
        }
    }
    (void)n_in; (void)out_size;
}

// round 9
// speedup vs baseline: 1.9046x; 1.0117x over previous
#include <cuda_runtime.h>
#include <cuda_fp16.h>

// DAGNN: CSR build + 10x SpMM hops (fp16 q-buffers, 5-slot rotation),
// R3-style uniform gather loop, pooling grouped at hops 5 and 10.
// N=100000, D=64, E=1600000, K=10.

#define MAX_N 100000
#define MAX_E 1600000
#define D 64
#define FULLMASK 0xffffffffu
#define NBUF 5

// ---------------- device scratch (static: allocation-free rule) ----------------
__device__ __align__(256) __half g_q[NBUF * (size_t)MAX_N * D];  // 64 MB
__device__ float g_norm[MAX_N];      // rsqrt(max(deg,1))
__device__ float g_norm2[MAX_N];     // 1/max(deg,1)
__device__ float g_invn[MAX_N];      // sqrt(max(deg,1)) = 1/norm
__device__ int   g_deg[MAX_N];
__device__ int   g_cursor[MAX_N];
__device__ int   g_rowptr[MAX_N + 1];
__device__ int   g_csr_src[MAX_E];
__device__ int   g_idx64;            // 1 if src/dst are int64, 0 if int32

// ---------------- k1: init + dtype probe ----------------
__global__ void init_kernel(const void* __restrict__ dst, int n) {
    if (blockIdx.x == 0) {
        // int64 values < 2^31 have zero odd 32-bit words; int32 ids are random.
        const unsigned* w = (const unsigned*)dst;
        int ok = (w[2 * threadIdx.x + 1] == 0u) ? 1 : 0;
        int all = __syncthreads_and(ok);
        if (threadIdx.x == 0) g_idx64 = all;
    }
    for (int i = blockIdx.x * blockDim.x + threadIdx.x; i < n;
         i += gridDim.x * blockDim.x) {
        g_deg[i] = 0;
        g_cursor[i] = 0;
    }
}

__device__ __forceinline__ int read_idx(const void* p, int i, int is64) {
    if (is64) return (int)((const long long*)p)[i];
    return ((const int*)p)[i];
}

// ---------------- k2: degree count ----------------
__global__ void deg_kernel(const void* __restrict__ dst, int e) {
    int is64 = g_idx64;
    for (int i = blockIdx.x * blockDim.x + threadIdx.x; i < e;
         i += gridDim.x * blockDim.x) {
        atomicAdd(&g_deg[read_idx(dst, i, is64)], 1);
    }
}

// ---------------- k3: norm terms + exclusive scan (one block) ----------------
__global__ void normscan_kernel(int n) {
    __shared__ int part[1024];
    int t = threadIdx.x;
    int chunk = (n + 1023) / 1024;
    int beg = t * chunk;
    int end = beg + chunk;
    if (beg > n) beg = n;
    if (end > n) end = n;
    int s = 0;
    for (int i = beg; i < end; ++i) {
        int d = g_deg[i];
        float df = fmaxf((float)d, 1.0f);
        g_norm2[i] = 1.0f / df;
        g_norm[i] = rsqrtf(df);
        g_invn[i] = sqrtf(df);
        s += d;
    }
    part[t] = s;
    __syncthreads();
    if (t == 0) {
        int acc = 0;
        for (int i = 0; i < 1024; ++i) { int v = part[i]; part[i] = acc; acc += v; }
    }
    __syncthreads();
    int acc = part[t];
    for (int i = beg; i < end; ++i) { g_rowptr[i] = acc; acc += g_deg[i]; }
    if (t == 1023) g_rowptr[n] = acc;
}

// ---------------- k4: CSR fill ----------------
__global__ void fill_kernel(const void* __restrict__ src,
                            const void* __restrict__ dst, int e) {
    int is64 = g_idx64;
    for (int i = blockIdx.x * blockDim.x + threadIdx.x; i < e;
         i += gridDim.x * blockDim.x) {
        int d = read_idx(dst, i, is64);
        int p = atomicAdd(&g_cursor[d], 1);
        g_csr_src[g_rowptr[d] + p] = read_idx(src, i, is64);
    }
}

// ---------------- k5: prep: out = sig(f.s)*f (write-only), q0 = norm*f --------
__global__ void prep_kernel(const float* __restrict__ feat,
                            const float* __restrict__ s,
                            float* __restrict__ out,
                            __half2* __restrict__ q0, int n) {
    int warp = (blockIdx.x * blockDim.x + threadIdx.x) >> 5;
    int lane = threadIdx.x & 31;
    if (warp >= n) return;
    int base = warp * 32 + lane;
    float2 f = ((const float2*)feat)[base];
    float2 sv = ((const float2*)s)[lane];
    float dot = f.x * sv.x + f.y * sv.y;
    #pragma unroll
    for (int off = 16; off; off >>= 1) dot += __shfl_xor_sync(FULLMASK, dot, off);
    float sig = 1.0f / (1.0f + __expf(-dot));
    float2 o; o.x = sig * f.x; o.y = sig * f.y;
    ((float2*)out)[base] = o;
    float nm = g_norm[warp];
    float2 g; g.x = nm * f.x; g.y = nm * f.y;
    q0[base] = __float22half2_rn(g);
}

// ---------------- hop (plain): q_t = norm2 * gather(q_{t-1}) ----------------
// R3-style: one warp per node, uniform index loads, compiler-batched gathers.
__global__ void hop_kernel(const __half2* __restrict__ qin,
                           __half2* __restrict__ qout, int n) {
    int warp = (blockIdx.x * blockDim.x + threadIdx.x) >> 5;
    int lane = threadIdx.x & 31;
    if (warp >= n) return;
    int beg = g_rowptr[warp];
    int end = g_rowptr[warp + 1];
    float a0 = 0.0f, a1 = 0.0f;
    #pragma unroll 4
    for (int j = beg; j < end; ++j) {
        int sn = g_csr_src[j];                           // uniform (L1-hit)
        float2 v = __half22float2(qin[sn * 32 + lane]);  // 128B coalesced
        a0 += v.x; a1 += v.y;
    }
    float n2 = g_norm2[warp];
    float2 g; g.x = n2 * a0; g.y = n2 * a1;
    qout[warp * 32 + lane] = __float22half2_rn(g);
}

// ---------------- hop + pool: current hop + 4 older hops -> out RMW ----------
__global__ void hop_pool_kernel(const __half2* __restrict__ qin,
                                __half2* __restrict__ qout,
                                const __half2* __restrict__ b1,
                                const __half2* __restrict__ b2,
                                const __half2* __restrict__ b3,
                                const __half2* __restrict__ b4,
                                const float* __restrict__ s,
                                float* __restrict__ out, int n) {
    int warp = (blockIdx.x * blockDim.x + threadIdx.x) >> 5;
    int lane = threadIdx.x & 31;
    if (warp >= n) return;
    int beg = g_rowptr[warp];
    int end = g_rowptr[warp + 1];
    float a0 = 0.0f, a1 = 0.0f;
    #pragma unroll 4
    for (int j = beg; j < end; ++j) {
        int sn = g_csr_src[j];
        float2 v = __half22float2(qin[sn * 32 + lane]);
        a0 += v.x; a1 += v.y;
    }
    int base = warp * 32 + lane;
    float2 sv = ((const float2*)s)[lane];
    float nm = g_norm[warp];
    float n2 = g_norm2[warp];
    float inv = g_invn[warp];

    // current hop h_t (in registers)
    float h0 = nm * a0, h1 = nm * a1;
    float dot = h0 * sv.x + h1 * sv.y;
    #pragma unroll
    for (int off = 16; off; off >>= 1) dot += __shfl_xor_sync(FULLMASK, dot, off);
    float sig = 1.0f / (1.0f + __expf(-dot));
    float c0 = sig * h0, c1 = sig * h1;

    // 4 older hops from rotation buffers (own-row reads, L2-hot)
    const __half2* bufs[4] = { b1, b2, b3, b4 };
    #pragma unroll
    for (int b = 0; b < 4; ++b) {
        float2 f = __half22float2(bufs[b][base]);
        float e0 = inv * f.x, e1 = inv * f.y;
        float d2 = e0 * sv.x + e1 * sv.y;
        #pragma unroll
        for (int off = 16; off; off >>= 1) d2 += __shfl_xor_sync(FULLMASK, d2, off);
        float sg = 1.0f / (1.0f + __expf(-d2));
        c0 += sg * e0; c1 += sg * e1;
    }

    qout[base] = __float22half2_rn(make_float2(n2 * a0, n2 * a1));

    float2* op = (float2*)out + base;
    float2 o = *op;
    o.x += c0; o.y += c1;
    *op = o;
}

// ---------------- launch ----------------
extern "C" void kernel_launch(void* const* d_in, const int* in_sizes, int n_in,
                              void* d_out, int out_size) {
    const float* feat = (const float*)d_in[0];
    const float* s    = (const float*)d_in[1];
    const void*  src  = d_in[2];
    const void*  dst  = d_in[3];
    float* out = (float*)d_out;

    int n = in_sizes[0] / D;
    int e = in_sizes[2];

    __half* qbase;
    cudaGetSymbolAddress((void**)&qbase, g_q);
    const size_t BUF = (size_t)MAX_N * (D / 2);       // half2 units per buffer
    __half2* B[NBUF];
    for (int i = 0; i < NBUF; ++i) B[i] = (__half2*)qbase + i * BUF;

    const int T = 256;
    int blkN = (n + T - 1) / T;
    int blkE = (e + T - 1) / T; if (blkE > 2048) blkE = 2048;
    int blkW = (int)(((size_t)n * 32 + T - 1) / T);   // one warp per node

    init_kernel<<<blkN, T>>>(dst, n);
    deg_kernel<<<blkE, T>>>(dst, e);
    normscan_kernel<<<1, 1024>>>(n);
    fill_kernel<<<blkE, T>>>(src, dst, e);
    prep_kernel<<<blkW, T>>>(feat, s, out, B[0], n);

    // hops: q_t lives in B[t % 5]; pool at t=5 (h1..h5) and t=10 (h6..h10)
    for (int t = 1; t <= 10; ++t) {
        const __half2* qin = B[(t - 1) % NBUF];
        __half2* qout = B[t % NBUF];
        if (t == 5 || t == 10) {
            hop_pool_kernel<<<blkW, T>>>(qin, qout, B[1], B[2], B[3], B[4],
                                         s, out, n);
        } else {
            hop_kernel<<<blkW, T>>>(qin, qout, n);
        }
    }
    (void)n_in; (void)out_size;
}

// round 10
// speedup vs baseline: 1.9315x; 1.0141x over previous
#include <cuda_runtime.h>
#include <cuda_fp16.h>

// DAGNN: CSR build + 10x SpMM hops (fp16 PING-PONG q-buffers — empirically
// optimal), pooling fused every 2 hops (q_{t-1} own-row read is L2-hot).
// N=100000, D=64, E=1600000, K=10.

#define MAX_N 100000
#define MAX_E 1600000
#define D 64
#define KHOPS 10
#define FULLMASK 0xffffffffu

// ---------------- device scratch (static: allocation-free rule) ----------------
__device__ __align__(256) __half g_bufA[(size_t)MAX_N * D];  // ping (12.8 MB)
__device__ __align__(256) __half g_bufB[(size_t)MAX_N * D];  // pong
__device__ float g_norm[MAX_N];      // rsqrt(max(deg,1))
__device__ float g_norm2[MAX_N];     // 1/max(deg,1)
__device__ float g_invn[MAX_N];      // sqrt(max(deg,1)) = 1/norm
__device__ int   g_deg[MAX_N];
__device__ int   g_cursor[MAX_N];
__device__ int   g_rowptr[MAX_N + 1];
__device__ int   g_csr_src[MAX_E];
__device__ int   g_idx64;            // 1 if src/dst are int64, 0 if int32

// ---------------- k1: init + dtype probe ----------------
__global__ void init_kernel(const void* __restrict__ dst, int n) {
    if (blockIdx.x == 0) {
        // int64 values < 2^31 have zero odd 32-bit words; int32 ids are random.
        const unsigned* w = (const unsigned*)dst;
        int ok = (w[2 * threadIdx.x + 1] == 0u) ? 1 : 0;
        int all = __syncthreads_and(ok);
        if (threadIdx.x == 0) g_idx64 = all;
    }
    for (int i = blockIdx.x * blockDim.x + threadIdx.x; i < n;
         i += gridDim.x * blockDim.x) {
        g_deg[i] = 0;
        g_cursor[i] = 0;
    }
}

__device__ __forceinline__ int read_idx(const void* p, int i, int is64) {
    if (is64) return (int)((const long long*)p)[i];
    return ((const int*)p)[i];
}

// ---------------- k2: degree count ----------------
__global__ void deg_kernel(const void* __restrict__ dst, int e) {
    int is64 = g_idx64;
    for (int i = blockIdx.x * blockDim.x + threadIdx.x; i < e;
         i += gridDim.x * blockDim.x) {
        atomicAdd(&g_deg[read_idx(dst, i, is64)], 1);
    }
}

// ---------------- k3: norm terms + exclusive scan (one block) ----------------
__global__ void normscan_kernel(int n) {
    __shared__ int part[1024];
    int t = threadIdx.x;
    int chunk = (n + 1023) / 1024;
    int beg = t * chunk;
    int end = beg + chunk;
    if (beg > n) beg = n;
    if (end > n) end = n;
    int s = 0;
    for (int i = beg; i < end; ++i) {
        int d = g_deg[i];
        float df = fmaxf((float)d, 1.0f);
        g_norm2[i] = 1.0f / df;
        g_norm[i] = rsqrtf(df);
        g_invn[i] = sqrtf(df);
        s += d;
    }
    part[t] = s;
    __syncthreads();
    if (t == 0) {
        int acc = 0;
        for (int i = 0; i < 1024; ++i) { int v = part[i]; part[i] = acc; acc += v; }
    }
    __syncthreads();
    int acc = part[t];
    for (int i = beg; i < end; ++i) { g_rowptr[i] = acc; acc += g_deg[i]; }
    if (t == 1023) g_rowptr[n] = acc;
}

// ---------------- k4: CSR fill ----------------
__global__ void fill_kernel(const void* __restrict__ src,
                            const void* __restrict__ dst, int e) {
    int is64 = g_idx64;
    for (int i = blockIdx.x * blockDim.x + threadIdx.x; i < e;
         i += gridDim.x * blockDim.x) {
        int d = read_idx(dst, i, is64);
        int p = atomicAdd(&g_cursor[d], 1);
        g_csr_src[g_rowptr[d] + p] = read_idx(src, i, is64);
    }
}

// ---------------- k5: prep: out = sig(f.s)*f (write-only), q0 = norm*f --------
__global__ void prep_kernel(const float* __restrict__ feat,
                            const float* __restrict__ s,
                            float* __restrict__ out,
                            __half2* __restrict__ q0, int n) {
    int warp = (blockIdx.x * blockDim.x + threadIdx.x) >> 5;
    int lane = threadIdx.x & 31;
    if (warp >= n) return;
    int base = warp * 32 + lane;
    float2 f = ((const float2*)feat)[base];
    float2 sv = ((const float2*)s)[lane];
    float dot = f.x * sv.x + f.y * sv.y;
    #pragma unroll
    for (int off = 16; off; off >>= 1) dot += __shfl_xor_sync(FULLMASK, dot, off);
    float sig = 1.0f / (1.0f + __expf(-dot));
    float2 o; o.x = sig * f.x; o.y = sig * f.y;
    ((float2*)out)[base] = o;
    float nm = g_norm[warp];
    float2 g; g.x = nm * f.x; g.y = nm * f.y;
    q0[base] = __float22half2_rn(g);
}

// ---------------- hop (odd t): q_t = norm2 * gather(q_{t-1}), no pooling ------
__global__ void hop_kernel(const __half2* __restrict__ qin,
                           __half2* __restrict__ qout, int n) {
    int warp = (blockIdx.x * blockDim.x + threadIdx.x) >> 5;
    int lane = threadIdx.x & 31;
    if (warp >= n) return;
    int beg = g_rowptr[warp];
    int end = g_rowptr[warp + 1];
    float a0 = 0.0f, a1 = 0.0f;
    #pragma unroll 8
    for (int j = beg; j < end; ++j) {
        int sn = g_csr_src[j];                           // uniform (L1-hit)
        float2 v = __half22float2(qin[sn * 32 + lane]);  // 128B coalesced
        a0 += v.x; a1 += v.y;
    }
    float n2 = g_norm2[warp];
    qout[warp * 32 + lane] = __float22half2_rn(make_float2(n2 * a0, n2 * a1));
}

// ---------------- hop (even t): also pool h_{t-1} (own row of qin) + h_t ------
__global__ void hop_pool2_kernel(const __half2* __restrict__ qin,
                                 __half2* __restrict__ qout,
                                 const float* __restrict__ s,
                                 float* __restrict__ out, int n) {
    int warp = (blockIdx.x * blockDim.x + threadIdx.x) >> 5;
    int lane = threadIdx.x & 31;
    if (warp >= n) return;
    int beg = g_rowptr[warp];
    int end = g_rowptr[warp + 1];
    float a0 = 0.0f, a1 = 0.0f;
    #pragma unroll 8
    for (int j = beg; j < end; ++j) {
        int sn = g_csr_src[j];
        float2 v = __half22float2(qin[sn * 32 + lane]);
        a0 += v.x; a1 += v.y;
    }
    int base = warp * 32 + lane;
    float2 sv = ((const float2*)s)[lane];
    float nm = g_norm[warp];
    float inv = g_invn[warp];

    // h_t from registers; h_{t-1} from own row of qin (L2-hot gather source)
    float h0 = nm * a0, h1 = nm * a1;
    float2 p = __half22float2(qin[base]);
    float e0 = inv * p.x, e1 = inv * p.y;

    float dt = h0 * sv.x + h1 * sv.y;
    float dp = e0 * sv.x + e1 * sv.y;
    #pragma unroll
    for (int off = 16; off; off >>= 1) {
        dt += __shfl_xor_sync(FULLMASK, dt, off);
        dp += __shfl_xor_sync(FULLMASK, dp, off);
    }
    float st_ = 1.0f / (1.0f + __expf(-dt));
    float sp_ = 1.0f / (1.0f + __expf(-dp));

    float n2 = g_norm2[warp];
    qout[base] = __float22half2_rn(make_float2(n2 * a0, n2 * a1));

    float2* op = (float2*)out + base;
    float2 o = *op;
    o.x += st_ * h0 + sp_ * e0;
    o.y += st_ * h1 + sp_ * e1;
    *op = o;
}

// ---------------- launch ----------------
extern "C" void kernel_launch(void* const* d_in, const int* in_sizes, int n_in,
                              void* d_out, int out_size) {
    const float* feat = (const float*)d_in[0];
    const float* s    = (const float*)d_in[1];
    const void*  src  = d_in[2];
    const void*  dst  = d_in[3];
    float* out = (float*)d_out;

    int n = in_sizes[0] / D;
    int e = in_sizes[2];

    __half *dA, *dB;
    cudaGetSymbolAddress((void**)&dA, g_bufA);
    cudaGetSymbolAddress((void**)&dB, g_bufB);

    const int T = 256;
    int blkN = (n + T - 1) / T;
    int blkE = (e + T - 1) / T; if (blkE > 2048) blkE = 2048;
    int blkW = (int)(((size_t)n * 32 + T - 1) / T);   // one warp per node

    init_kernel<<<blkN, T>>>(dst, n);
    deg_kernel<<<blkE, T>>>(dst, e);
    normscan_kernel<<<1, 1024>>>(n);
    fill_kernel<<<blkE, T>>>(src, dst, e);
    prep_kernel<<<blkW, T>>>(feat, s, out, (__half2*)dA, n);

    __half2* qin = (__half2*)dA;
    __half2* qout = (__half2*)dB;
    for (int t = 1; t <= KHOPS; ++t) {
        if ((t & 1) == 0) {
            hop_pool2_kernel<<<blkW, T>>>(qin, qout, s, out, n);
        } else {
            hop_kernel<<<blkW, T>>>(qin, qout, n);
        }
        __half2* tmp = qin; qin = qout; qout = tmp;
    }
    (void)n_in; (void)out_size;
}

// round 12
// speedup vs baseline: 2.3526x; 1.2180x over previous
#include <cuda_runtime.h>
#include <cuda_fp16.h>

// DAGNN: R3-champion hop structure (fp16 ping-pong, fused every-hop pooling,
// unroll-4 uniform gather) + vectorized build phase.
// N=100000, D=64, E=1600000, K=10.

#define MAX_N 100000
#define MAX_E 1600000
#define D 64
#define KHOPS 10
#define FULLMASK 0xffffffffu

// ---------------- device scratch (static: allocation-free rule) ----------------
__device__ __align__(256) __half g_bufA[(size_t)MAX_N * D];  // ping (12.8 MB)
__device__ __align__(256) __half g_bufB[(size_t)MAX_N * D];  // pong
__device__ float g_norm[MAX_N];      // rsqrt(max(deg,1))
__device__ int   g_deg[MAX_N];
__device__ int   g_cursor[MAX_N];
__device__ int   g_rowptr[MAX_N + 1];
__device__ int   g_csr_src[MAX_E];
__device__ int   g_idx64;            // 1 if src/dst are int64, 0 if int32

// ---------------- k1: init + dtype probe ----------------
__global__ void init_kernel(const void* __restrict__ dst, int n) {
    if (blockIdx.x == 0) {
        // int64 values < 2^31 have zero odd 32-bit words; int32 ids are random.
        const unsigned* w = (const unsigned*)dst;
        int ok = (w[2 * threadIdx.x + 1] == 0u) ? 1 : 0;
        int all = __syncthreads_and(ok);
        if (threadIdx.x == 0) g_idx64 = all;
    }
    for (int i = blockIdx.x * blockDim.x + threadIdx.x; i < n;
         i += gridDim.x * blockDim.x) {
        g_deg[i] = 0;
        g_cursor[i] = 0;
    }
}

// ---------------- k2: degree count (vectorized index loads) ----------------
__global__ void deg_kernel(const void* __restrict__ dst, int e) {
    int is64 = g_idx64;
    int tid = blockIdx.x * blockDim.x + threadIdx.x;
    int nth = gridDim.x * blockDim.x;
    if (!is64) {
        const int4* v = (const int4*)dst;
        int e4 = e >> 2;
        for (int i = tid; i < e4; i += nth) {
            int4 x = v[i];
            atomicAdd(&g_deg[x.x], 1);
            atomicAdd(&g_deg[x.y], 1);
            atomicAdd(&g_deg[x.z], 1);
            atomicAdd(&g_deg[x.w], 1);
        }
        for (int i = (e4 << 2) + tid; i < e; i += nth)
            atomicAdd(&g_deg[((const int*)dst)[i]], 1);
    } else {
        const longlong2* v = (const longlong2*)dst;
        int e2 = e >> 1;
        for (int i = tid; i < e2; i += nth) {
            longlong2 x = v[i];
            atomicAdd(&g_deg[(int)x.x], 1);
            atomicAdd(&g_deg[(int)x.y], 1);
        }
        for (int i = (e2 << 1) + tid; i < e; i += nth)
            atomicAdd(&g_deg[(int)((const long long*)dst)[i]], 1);
    }
}

// ---------------- k3: norm + exclusive scan (one block) ----------------
__global__ void normscan_kernel(int n) {
    __shared__ int part[1024];
    int t = threadIdx.x;
    int chunk = (n + 1023) / 1024;
    int beg = t * chunk;
    int end = beg + chunk;
    if (beg > n) beg = n;
    if (end > n) end = n;
    int s = 0;
    for (int i = beg; i < end; ++i) {
        int d = g_deg[i];
        g_norm[i] = rsqrtf(fmaxf((float)d, 1.0f));
        s += d;
    }
    part[t] = s;
    __syncthreads();
    if (t == 0) {
        int acc = 0;
        for (int i = 0; i < 1024; ++i) { int v = part[i]; part[i] = acc; acc += v; }
    }
    __syncthreads();
    int acc = part[t];
    for (int i = beg; i < end; ++i) { g_rowptr[i] = acc; acc += g_deg[i]; }
    if (t == 1023) g_rowptr[n] = acc;
}

// ---------------- k4: CSR fill (vectorized index loads) ----------------
__device__ __forceinline__ void fill_one(int d, int sv) {
    int p = atomicAdd(&g_cursor[d], 1);
    g_csr_src[g_rowptr[d] + p] = sv;
}

__global__ void fill_kernel(const void* __restrict__ src,
                            const void* __restrict__ dst, int e) {
    int is64 = g_idx64;
    int tid = blockIdx.x * blockDim.x + threadIdx.x;
    int nth = gridDim.x * blockDim.x;
    if (!is64) {
        const int4* vd = (const int4*)dst;
        const int4* vs = (const int4*)src;
        int e4 = e >> 2;
        for (int i = tid; i < e4; i += nth) {
            int4 d = vd[i];
            int4 s = vs[i];
            fill_one(d.x, s.x);
            fill_one(d.y, s.y);
            fill_one(d.z, s.z);
            fill_one(d.w, s.w);
        }
        for (int i = (e4 << 2) + tid; i < e; i += nth)
            fill_one(((const int*)dst)[i], ((const int*)src)[i]);
    } else {
        const longlong2* vd = (const longlong2*)dst;
        const longlong2* vs = (const longlong2*)src;
        int e2 = e >> 1;
        for (int i = tid; i < e2; i += nth) {
            longlong2 d = vd[i];
            longlong2 s = vs[i];
            fill_one((int)d.x, (int)s.x);
            fill_one((int)d.y, (int)s.y);
        }
        for (int i = (e2 << 1) + tid; i < e; i += nth)
            fill_one((int)((const long long*)dst)[i],
                     (int)((const long long*)src)[i]);
    }
}

// ---------------- k5: prep: out = sig(f.s)*f, q0 = norm*f ----------------
__global__ void prep_kernel(const float* __restrict__ feat,
                            const float* __restrict__ s,
                            float* __restrict__ out,
                            __half2* __restrict__ q0, int n) {
    int warp = (blockIdx.x * blockDim.x + threadIdx.x) >> 5;
    int lane = threadIdx.x & 31;
    if (warp >= n) return;
    int base = warp * 32 + lane;
    float2 f = ((const float2*)feat)[base];
    float2 sv = ((const float2*)s)[lane];
    float dot = f.x * sv.x + f.y * sv.y;
    #pragma unroll
    for (int off = 16; off; off >>= 1) dot += __shfl_xor_sync(FULLMASK, dot, off);
    float sig = 1.0f / (1.0f + __expf(-dot));
    float2 o; o.x = sig * f.x; o.y = sig * f.y;
    ((float2*)out)[base] = o;
    float nm = g_norm[warp];
    float2 g; g.x = nm * f.x; g.y = nm * f.y;
    q0[base] = __float22half2_rn(g);
}

// ---------------- hop: gather-sum (fp16 in, fp32 accum), fused pooling --------
// EXACT R3-champion structure: unroll 4, every-hop sigmoid-pool RMW on out.
__global__ void hop_kernel(const __half2* __restrict__ qin,
                           __half2* __restrict__ qout,
                           float* __restrict__ out,
                           const float* __restrict__ s, int n) {
    int warp = (blockIdx.x * blockDim.x + threadIdx.x) >> 5;
    int lane = threadIdx.x & 31;
    if (warp >= n) return;
    int beg = g_rowptr[warp];
    int end = g_rowptr[warp + 1];
    float a0 = 0.0f, a1 = 0.0f;
    #pragma unroll 4
    for (int j = beg; j < end; ++j) {
        int sn = g_csr_src[j];                           // uniform (L1-hit)
        float2 v = __half22float2(qin[sn * 32 + lane]);  // 128B coalesced
        a0 += v.x; a1 += v.y;
    }
    float nm = g_norm[warp];
    float h0 = a0 * nm, h1 = a1 * nm;                    // h_t (fp32)
    float2 sv = ((const float2*)s)[lane];
    float dot = h0 * sv.x + h1 * sv.y;
    #pragma unroll
    for (int off = 16; off; off >>= 1) dot += __shfl_xor_sync(FULLMASK, dot, off);
    float sig = 1.0f / (1.0f + __expf(-dot));
    int base = warp * 32 + lane;
    float2* op = (float2*)out + base;
    float2 o = *op;
    o.x += sig * h0; o.y += sig * h1;
    *op = o;
    float2 g; g.x = nm * h0; g.y = nm * h1;              // q_t for next hop
    qout[base] = __float22half2_rn(g);
}

// ---------------- launch ----------------
extern "C" void kernel_launch(void* const* d_in, const int* in_sizes, int n_in,
                              void* d_out, int out_size) {
    const float* feat = (const float*)d_in[0];
    const float* s    = (const float*)d_in[1];
    const void*  src  = d_in[2];
    const void*  dst  = d_in[3];
    float* out = (float*)d_out;

    int n = in_sizes[0] / D;
    int e = in_sizes[2];

    __half *dA, *dB;
    cudaGetSymbolAddress((void**)&dA, g_bufA);
    cudaGetSymbolAddress((void**)&dB, g_bufB);

    const int T = 256;
    int blkN = (n + T - 1) / T;
    int blkE = ((e >> 2) + T - 1) / T; if (blkE > 1184) blkE = 1184;
    int blkW = (int)(((size_t)n * 32 + T - 1) / T);   // one warp per node

    init_kernel<<<blkN, T>>>(dst, n);
    deg_kernel<<<blkE, T>>>(dst, e);
    normscan_kernel<<<1, 1024>>>(n);
    fill_kernel<<<blkE, T>>>(src, dst, e);
    prep_kernel<<<blkW, T>>>(feat, s, out, (__half2*)dA, n);

    __half2* qin = (__half2*)dA;
    __half2* qout = (__half2*)dB;
    for (int t = 0; t < KHOPS; ++t) {
        hop_kernel<<<blkW, T>>>(qin, qout, out, s, n);
        __half2* tmp = qin; qin = qout; qout = tmp;
    }
    (void)n_in; (void)out_size;
}